// round 2
// baseline (speedup 1.0000x reference)
#include <cuda_runtime.h>
#include <math.h>

// Problem constants (fixed shapes from reference)
#define BSZ     4
#define LSEQ    2048
#define DMODEL  1024
#define DSTATE  16
#define DCONV   4
#define DINNER  2048
// Tokens M = BSZ*LSEQ = 8192
// GEMM1: (8192 x 1024) @ (1024 x 4096) -> xz
// GEMM2: (8192 x 2048) @ (2048 x 1024) -> out

// Scratch (no cudaMalloc allowed): static device buffers (~201 MB total).
__device__ float g_xz[(size_t)BSZ * LSEQ * 2 * DINNER];   // (8192, 4096)
__device__ float g_y [(size_t)BSZ * LSEQ * DINNER];       // (8192, 2048)

// ---------------------------------------------------------------------------
// Tiled FP32 SGEMM, double-buffered SMEM: C[M,N] = A[M,K] * B[K,N], row-major.
// BM=BN=128, BK=8, 256 threads, 8x8 per-thread microtile, float4 loads/stores.
// All dims are multiples of the tile sizes -> no bounds checks.
// ---------------------------------------------------------------------------
__global__ __launch_bounds__(256) void sgemm128(
    int M, int N, int K,
    const float* __restrict__ A,
    const float* __restrict__ Bm,
    float* __restrict__ C)
{
    constexpr int BM = 128, BN = 128, BK = 8, TM = 8, TN = 8;
    __shared__ float As[2][BK][BM];
    __shared__ float Bs[2][BK][BN];

    const int tid = threadIdx.x;

    const float* Ap = A  + (size_t)blockIdx.y * BM * K;
    const float* Bp = Bm + (size_t)blockIdx.x * BN;
    float*       Cp = C  + (size_t)blockIdx.y * BM * N + (size_t)blockIdx.x * BN;

    // A tile load: 128 rows x 8 cols, one float4 per thread (transposed store)
    const int aRow = tid >> 1;            // 0..127
    const int aCol = (tid & 1) * 4;       // 0 or 4
    // B tile load: 8 rows x 128 cols, one float4 per thread
    const int bRow = tid >> 5;            // 0..7
    const int bCol = (tid & 31) * 4;      // 0..124
    // Microtile position
    const int tRow = (tid >> 4) * TM;     // 0..120
    const int tCol = (tid & 15) * TN;     // 0..120

    float acc[TM][TN];
    #pragma unroll
    for (int i = 0; i < TM; i++)
        #pragma unroll
        for (int j = 0; j < TN; j++) acc[i][j] = 0.0f;

    const int nTiles = K / BK;

    // Preload tile 0 into buffer 0
    {
        float4 a4 = *reinterpret_cast<const float4*>(Ap + (size_t)aRow * K + aCol);
        As[0][aCol + 0][aRow] = a4.x;
        As[0][aCol + 1][aRow] = a4.y;
        As[0][aCol + 2][aRow] = a4.z;
        As[0][aCol + 3][aRow] = a4.w;
        *reinterpret_cast<float4*>(&Bs[0][bRow][bCol]) =
            *reinterpret_cast<const float4*>(Bp + (size_t)bRow * N + bCol);
    }
    __syncthreads();

    for (int t = 0; t < nTiles; t++) {
        const int cur = t & 1;
        const int nxt = cur ^ 1;

        float4 a4, b4;
        const bool hasNext = (t + 1) < nTiles;
        if (hasNext) {
            const float* Apn = Ap + (size_t)(t + 1) * BK;
            const float* Bpn = Bp + (size_t)(t + 1) * BK * N;
            a4 = *reinterpret_cast<const float4*>(Apn + (size_t)aRow * K + aCol);
            b4 = *reinterpret_cast<const float4*>(Bpn + (size_t)bRow * N + bCol);
        }

        #pragma unroll
        for (int k = 0; k < BK; k++) {
            float ra[TM], rb[TN];
            #pragma unroll
            for (int i = 0; i < TM; i++) ra[i] = As[cur][k][tRow + i];
            #pragma unroll
            for (int j = 0; j < TN; j++) rb[j] = Bs[cur][k][tCol + j];
            #pragma unroll
            for (int i = 0; i < TM; i++)
                #pragma unroll
                for (int j = 0; j < TN; j++)
                    acc[i][j] = fmaf(ra[i], rb[j], acc[i][j]);
        }

        if (hasNext) {
            As[nxt][aCol + 0][aRow] = a4.x;
            As[nxt][aCol + 1][aRow] = a4.y;
            As[nxt][aCol + 2][aRow] = a4.z;
            As[nxt][aCol + 3][aRow] = a4.w;
            *reinterpret_cast<float4*>(&Bs[nxt][bRow][bCol]) = b4;
        }
        __syncthreads();
    }

    #pragma unroll
    for (int i = 0; i < TM; i++) {
        float4* crow = reinterpret_cast<float4*>(Cp + (size_t)(tRow + i) * N + tCol);
        crow[0] = make_float4(acc[i][0], acc[i][1], acc[i][2], acc[i][3]);
        crow[1] = make_float4(acc[i][4], acc[i][5], acc[i][6], acc[i][7]);
    }
}

// ---------------------------------------------------------------------------
// Fused: causal depthwise conv (k=4) + diagonal SSM scan (16 states in regs)
// + silu(z) gate. One thread per (b, d) channel; scans t = 0..L-1.
// u = xz[..., :DINNER], z = xz[..., DINNER:].  Writes g_y[(b,t,d)].
// Loads are 8-deep unrolled & front-batched for MLP.
// ---------------------------------------------------------------------------
__global__ __launch_bounds__(64) void conv_scan_gate(
    const float* __restrict__ conv_w,   // (DINNER, 1, DCONV)
    const float* __restrict__ conv_b,   // (DINNER,)
    const float* __restrict__ A_log,    // (DSTATE, DINNER)
    const float* __restrict__ D_param)  // (DINNER,)
{
    const int gid = blockIdx.x * blockDim.x + threadIdx.x;  // 0..8191
    const int b = gid >> 11;        // / DINNER
    const int d = gid & (DINNER - 1);

    const float* xz   = g_xz + (size_t)b * LSEQ * (2 * DINNER);
    float*       yout = g_y  + (size_t)b * LSEQ * DINNER;

    const float w0 = conv_w[d * DCONV + 0];
    const float w1 = conv_w[d * DCONV + 1];
    const float w2 = conv_w[d * DCONV + 2];
    const float w3 = conv_w[d * DCONV + 3];
    const float bias = conv_b[d];
    const float Dp = D_param[d];

    float Aval[DSTATE];
    #pragma unroll
    for (int s = 0; s < DSTATE; s++)
        Aval[s] = -expf(A_log[s * DINNER + d]);

    float st[DSTATE];
    #pragma unroll
    for (int s = 0; s < DSTATE; s++) st[s] = 0.0f;

    float x0 = 0.f, x1 = 0.f, x2 = 0.f, x3 = 0.f;  // conv window (left zero-pad)

    constexpr int U = 8;
    for (int t0 = 0; t0 < LSEQ; t0 += U) {
        float uv[U], zv[U];
        #pragma unroll
        for (int i = 0; i < U; i++) {
            const size_t off = (size_t)(t0 + i) * (2 * DINNER) + d;
            uv[i] = xz[off];
            zv[i] = xz[off + DINNER];
        }
        #pragma unroll
        for (int i = 0; i < U; i++) {
            x0 = x1; x1 = x2; x2 = x3; x3 = uv[i];
            // uc[t] = sum_j w[j] * u[t-3+j] + bias
            float uc = fmaf(w0, x0, fmaf(w1, x1, fmaf(w2, x2, fmaf(w3, x3, bias))));
            float acc = Dp * uc;
            #pragma unroll
            for (int s = 0; s < DSTATE; s++) {
                st[s] = fmaf(st[s], Aval[s], uc);
                acc += st[s];
            }
            const float z = zv[i];
            const float sig = 1.0f / (1.0f + expf(-z));
            yout[(size_t)(t0 + i) * DINNER + d] = acc * (z * sig);
        }
    }
}

// ---------------------------------------------------------------------------
extern "C" void kernel_launch(void* const* d_in, const int* in_sizes, int n_in,
                              void* d_out, int out_size)
{
    const float* x       = (const float*)d_in[0];  // (B, L, DMODEL)
    const float* W_in    = (const float*)d_in[1];  // (DMODEL, 2*DINNER)
    const float* conv_w  = (const float*)d_in[2];  // (DINNER, 1, DCONV)
    const float* conv_b  = (const float*)d_in[3];  // (DINNER,)
    const float* A_log   = (const float*)d_in[4];  // (DSTATE, DINNER)
    const float* D_param = (const float*)d_in[5];  // (DINNER,)
    const float* W_out   = (const float*)d_in[6];  // (DINNER, DMODEL)
    float* out = (float*)d_out;                    // (B, L, DMODEL)

    float *xz_ptr, *y_ptr;
    cudaGetSymbolAddress((void**)&xz_ptr, g_xz);
    cudaGetSymbolAddress((void**)&y_ptr,  g_y);

    const int M = BSZ * LSEQ;           // 8192

    // GEMM1: xz = x @ W_in   (8192 x 4096, K=1024)
    {
        dim3 grid((2 * DINNER) / 128, M / 128);   // (32, 64)
        sgemm128<<<grid, 256>>>(M, 2 * DINNER, DMODEL, x, W_in, xz_ptr);
    }

    // Fused conv + scan + gate -> g_y  (8192 channels, 64 thr/block x 128 blocks)
    conv_scan_gate<<<(BSZ * DINNER) / 64, 64>>>(conv_w, conv_b, A_log, D_param);

    // GEMM2: out = y @ W_out  (8192 x 1024, K=2048)
    {
        dim3 grid(DMODEL / 128, M / 128);         // (8, 64)
        sgemm128<<<grid, 256>>>(M, DMODEL, DINNER, y_ptr, W_out, out);
    }
}

// round 6
// speedup vs baseline: 2.2078x; 2.2078x over previous
#include <cuda_runtime.h>
#include <cuda_bf16.h>
#include <math.h>
#include <stdint.h>

// Problem constants (fixed shapes)
#define BSZ     4
#define LSEQ    2048
#define DMODEL  1024
#define DSTATE  16
#define DCONV   4
#define DINNER  2048
#define MTOK    (BSZ * LSEQ)            // 8192 tokens

// ---------------------------------------------------------------------------
// Static device scratch (no cudaMalloc allowed)
// ---------------------------------------------------------------------------
__device__ float         g_xz[(size_t)MTOK * 2 * DINNER];       // (8192, 4096) fp32
__device__ __nv_bfloat16 g_xhi[(size_t)MTOK * DMODEL];          // x split hi
__device__ __nv_bfloat16 g_xlo[(size_t)MTOK * DMODEL];          // x split lo
__device__ __nv_bfloat16 g_WinT_hi[(size_t)2 * DINNER * DMODEL];// W_in^T (4096,1024)
__device__ __nv_bfloat16 g_WinT_lo[(size_t)2 * DINNER * DMODEL];
__device__ __nv_bfloat16 g_WoutT_hi[(size_t)DMODEL * DINNER];   // W_out^T (1024,2048)
__device__ __nv_bfloat16 g_WoutT_lo[(size_t)DMODEL * DINNER];
__device__ __nv_bfloat16 g_yhi[(size_t)MTOK * DINNER];          // scan output hi
__device__ __nv_bfloat16 g_ylo[(size_t)MTOK * DINNER];          // scan output lo

// ---------------------------------------------------------------------------
// PTX helpers (sm_80+ only: ldmatrix / mma.sync / cp.async — all legal on sm_100)
// ---------------------------------------------------------------------------
__device__ __forceinline__ uint32_t smem_u32(const void* p) {
    uint32_t a;
    asm("{ .reg .u64 t; cvta.to.shared.u64 t, %1; cvt.u32.u64 %0, t; }"
        : "=r"(a) : "l"(p));
    return a;
}

__device__ __forceinline__ void ldsm_x4(uint32_t* r, uint32_t addr) {
    asm volatile("ldmatrix.sync.aligned.m8n8.x4.shared.b16 {%0,%1,%2,%3}, [%4];"
                 : "=r"(r[0]), "=r"(r[1]), "=r"(r[2]), "=r"(r[3]) : "r"(addr));
}

__device__ __forceinline__ void mma_bf16(float* c, const uint32_t* a,
                                         uint32_t b0, uint32_t b1) {
    asm volatile(
        "mma.sync.aligned.m16n8k16.row.col.f32.bf16.bf16.f32 "
        "{%0,%1,%2,%3}, {%4,%5,%6,%7}, {%8,%9}, {%0,%1,%2,%3};"
        : "+f"(c[0]), "+f"(c[1]), "+f"(c[2]), "+f"(c[3])
        : "r"(a[0]), "r"(a[1]), "r"(a[2]), "r"(a[3]), "r"(b0), "r"(b1));
}

__device__ __forceinline__ void cp_async16(uint32_t saddr, const void* gptr) {
    asm volatile("cp.async.cg.shared.global [%0], [%1], 16;"
                 :: "r"(saddr), "l"(gptr));
}
#define CP_COMMIT() asm volatile("cp.async.commit_group;" ::: "memory")
#define CP_WAIT(n)  asm volatile("cp.async.wait_group %0;" :: "n"(n) : "memory")

// ---------------------------------------------------------------------------
// Split-precision bf16 warp-MMA GEMM:  C[M,N] = A[M,K] @ B[N,K]^T  (fp32 out)
//   A as Ahi/Alo bf16 [M,K] row-major; B as Bhi/Blo bf16 [N,K] row-major.
//   3 passes accumulated in registers: hi*hi + hi*lo + lo*hi  (Ootomo bf16x3)
// CTA tile 128x128, BK=64, 256 threads (8 warps, 4x2), cp.async double buffer.
// SW128 swizzle: 16B chunk index ^= (row & 7)  -> conflict-free ldmatrix.
// ---------------------------------------------------------------------------
__global__ __launch_bounds__(256, 1) void gemm_bf16x3(
    int M, int N, int K,
    const __nv_bfloat16* __restrict__ Ahi,
    const __nv_bfloat16* __restrict__ Alo,
    const __nv_bfloat16* __restrict__ Bhi,
    const __nv_bfloat16* __restrict__ Blo,
    float* __restrict__ C)
{
    constexpr int BK = 64;                    // k elems per tile (128 bytes)
    constexpr int TILE_B = 128 * 128;         // bytes per operand tile
    constexpr int STAGE_B = TILE_B * 4;       // Ahi, Alo, Bhi, Blo = 64KB

    extern __shared__ char dsmem_raw[];
    const uint32_t raw_u32 = smem_u32(dsmem_raw);
    const uint32_t base = (raw_u32 + 1023u) & ~1023u;

    const int tid = threadIdx.x;
    const int wid = tid >> 5;
    const int lane = tid & 31;
    const int warpM = wid >> 1;               // 0..3 -> 32-row slice
    const int warpN = wid & 1;                // 0..1 -> 64-col slice
    const int blockRow = blockIdx.y;
    const int blockCol = blockIdx.x;

    const __nv_bfloat16* opSrc[4] = { Ahi, Alo, Bhi, Blo };

    // Issue one 64KB stage of cp.asyncs: 4096 16B chunks, 16 per thread.
    auto loadStageAsync = [&](int stage, int k0) {
        #pragma unroll
        for (int i = 0; i < 16; i++) {
            const int idx = tid + 256 * i;
            const int operand = idx >> 10;        // 0..3
            const int rem = idx & 1023;
            const int row = rem >> 3;             // 0..127
            const int chunk = rem & 7;            // 0..7
            const int gRow = (operand < 2 ? blockRow : blockCol) * 128 + row;
            const __nv_bfloat16* src =
                opSrc[operand] + (size_t)gRow * K + k0 + chunk * 8;
            const uint32_t saddr = base + stage * STAGE_B + operand * TILE_B
                                 + row * 128 + ((chunk ^ (row & 7)) << 4);
            cp_async16(saddr, src);
        }
    };

    float acc[2][8][4];                       // [mtile][n8tile][frag]
    #pragma unroll
    for (int m = 0; m < 2; m++)
        #pragma unroll
        for (int n = 0; n < 8; n++)
            #pragma unroll
            for (int j = 0; j < 4; j++) acc[m][n][j] = 0.0f;

    const int nK = K / BK;
    loadStageAsync(0, 0);
    CP_COMMIT();

    for (int t = 0; t < nK; t++) {
        const int cur = t & 1;
        if (t + 1 < nK) {
            loadStageAsync(cur ^ 1, (t + 1) * BK);
            CP_COMMIT();
            CP_WAIT(1);                       // current stage complete
        } else {
            CP_WAIT(0);
        }
        __syncthreads();

        const uint32_t sA[2] = { base + cur * STAGE_B + 0 * TILE_B,
                                 base + cur * STAGE_B + 1 * TILE_B };
        const uint32_t sB[2] = { base + cur * STAGE_B + 2 * TILE_B,
                                 base + cur * STAGE_B + 3 * TILE_B };

        #pragma unroll
        for (int ks = 0; ks < 4; ks++) {
            const int chunk = ks * 2 + (lane >> 4);   // 16B chunk for this lane

            // A fragments: [op][mtile][4]
            uint32_t afr[2][2][4];
            #pragma unroll
            for (int o = 0; o < 2; o++)
                #pragma unroll
                for (int mt = 0; mt < 2; mt++) {
                    const int row = warpM * 32 + mt * 16 + (lane & 15);
                    const uint32_t addr =
                        sA[o] + row * 128 + ((chunk ^ (row & 7)) << 4);
                    ldsm_x4(afr[o][mt], addr);
                }

            // B fragments: x4 covers two n8 tiles. [op][npair][4]
            uint32_t bfr[2][4][4];
            #pragma unroll
            for (int o = 0; o < 2; o++)
                #pragma unroll
                for (int np = 0; np < 4; np++) {
                    const int row = warpN * 64 + np * 16 + (lane & 15);
                    const uint32_t addr =
                        sB[o] + row * 128 + ((chunk ^ (row & 7)) << 4);
                    ldsm_x4(bfr[o][np], addr);
                }

            // r0=(n0-7,k0-7) r1=(n8-15,k0-7) r2=(n0-7,k8-15) r3=(n8-15,k8-15)
            #pragma unroll
            for (int mt = 0; mt < 2; mt++)
                #pragma unroll
                for (int np = 0; np < 4; np++)
                    #pragma unroll
                    for (int h = 0; h < 2; h++) {
                        float* a4 = acc[mt][np * 2 + h];
                        const uint32_t bh0 = bfr[0][np][h];
                        const uint32_t bh1 = bfr[0][np][h + 2];
                        const uint32_t bl0 = bfr[1][np][h];
                        const uint32_t bl1 = bfr[1][np][h + 2];
                        mma_bf16(a4, afr[0][mt], bh0, bh1);   // hi*hi
                        mma_bf16(a4, afr[0][mt], bl0, bl1);   // hi*lo
                        mma_bf16(a4, afr[1][mt], bh0, bh1);   // lo*hi
                    }
        }
        __syncthreads();
    }

    // Epilogue: c0,c1 -> (row g, col 2t..2t+1); c2,c3 -> row g+8
    const int g = lane >> 2;
    const int tcol = (lane & 3) * 2;
    #pragma unroll
    for (int mt = 0; mt < 2; mt++) {
        const int r0 = blockRow * 128 + warpM * 32 + mt * 16 + g;
        #pragma unroll
        for (int n = 0; n < 8; n++) {
            const int col = blockCol * 128 + warpN * 64 + n * 8 + tcol;
            float2 v01 = make_float2(acc[mt][n][0], acc[mt][n][1]);
            float2 v23 = make_float2(acc[mt][n][2], acc[mt][n][3]);
            *reinterpret_cast<float2*>(C + (size_t)r0 * N + col) = v01;
            *reinterpret_cast<float2*>(C + (size_t)(r0 + 8) * N + col) = v23;
        }
    }
}

// ---------------------------------------------------------------------------
// Elementwise fp32 -> (hi, lo) bf16 split.  n4 = n/4 float4 groups.
// ---------------------------------------------------------------------------
__global__ __launch_bounds__(256) void split_f32(
    const float* __restrict__ in,
    __nv_bfloat16* __restrict__ hi,
    __nv_bfloat16* __restrict__ lo,
    int n4)
{
    const int idx = blockIdx.x * blockDim.x + threadIdx.x;
    if (idx >= n4) return;
    const float4 v = reinterpret_cast<const float4*>(in)[idx];
    const float f[4] = { v.x, v.y, v.z, v.w };
    __nv_bfloat16 h[4], l[4];
    #pragma unroll
    for (int i = 0; i < 4; i++) {
        h[i] = __float2bfloat16(f[i]);
        l[i] = __float2bfloat16(f[i] - __bfloat162float(h[i]));
    }
    reinterpret_cast<uint2*>(hi)[idx] = *reinterpret_cast<uint2*>(h);
    reinterpret_cast<uint2*>(lo)[idx] = *reinterpret_cast<uint2*>(l);
}

// ---------------------------------------------------------------------------
// Transposed split: W[K,N] fp32 -> Th/Tl[N,K] bf16.  32x32 tiles, 32x8 threads.
// ---------------------------------------------------------------------------
__global__ __launch_bounds__(256) void transpose_split(
    const float* __restrict__ W,
    __nv_bfloat16* __restrict__ Th,
    __nv_bfloat16* __restrict__ Tl,
    int K, int N)
{
    __shared__ float tile[32][33];
    const int k0 = blockIdx.y * 32;
    const int n0 = blockIdx.x * 32;
    const int tx = threadIdx.x;       // 0..31
    const int ty = threadIdx.y;       // 0..7

    #pragma unroll
    for (int r = ty; r < 32; r += 8)
        tile[r][tx] = W[(size_t)(k0 + r) * N + n0 + tx];
    __syncthreads();

    #pragma unroll
    for (int r = ty; r < 32; r += 8) {
        const float v = tile[tx][r];              // = W[k0+tx][n0+r]
        const __nv_bfloat16 h = __float2bfloat16(v);
        const __nv_bfloat16 l = __float2bfloat16(v - __bfloat162float(h));
        const size_t o = (size_t)(n0 + r) * K + k0 + tx;
        Th[o] = h;
        Tl[o] = l;
    }
}

// ---------------------------------------------------------------------------
// Fused: causal depthwise conv (k=4) + diagonal SSM scan + silu(z) gate.
// One thread per (b, d) channel.  Emits y as hi/lo bf16 split for GEMM2.
// ---------------------------------------------------------------------------
__global__ __launch_bounds__(64) void conv_scan_gate(
    const float* __restrict__ conv_w,
    const float* __restrict__ conv_b,
    const float* __restrict__ A_log,
    const float* __restrict__ D_param)
{
    const int gid = blockIdx.x * blockDim.x + threadIdx.x;  // 0..8191
    const int b = gid >> 11;
    const int d = gid & (DINNER - 1);

    const float* xz = g_xz + (size_t)b * LSEQ * (2 * DINNER);
    __nv_bfloat16* yh = g_yhi + (size_t)b * LSEQ * DINNER;
    __nv_bfloat16* yl = g_ylo + (size_t)b * LSEQ * DINNER;

    const float w0 = conv_w[d * DCONV + 0];
    const float w1 = conv_w[d * DCONV + 1];
    const float w2 = conv_w[d * DCONV + 2];
    const float w3 = conv_w[d * DCONV + 3];
    const float bias = conv_b[d];
    const float Dp = D_param[d];

    float Aval[DSTATE];
    #pragma unroll
    for (int s = 0; s < DSTATE; s++)
        Aval[s] = -expf(A_log[s * DINNER + d]);

    float st[DSTATE];
    #pragma unroll
    for (int s = 0; s < DSTATE; s++) st[s] = 0.0f;

    float x0 = 0.f, x1 = 0.f, x2 = 0.f, x3 = 0.f;

    constexpr int U = 8;
    for (int t0 = 0; t0 < LSEQ; t0 += U) {
        float uv[U], zv[U];
        #pragma unroll
        for (int i = 0; i < U; i++) {
            const size_t off = (size_t)(t0 + i) * (2 * DINNER) + d;
            uv[i] = xz[off];
            zv[i] = xz[off + DINNER];
        }
        #pragma unroll
        for (int i = 0; i < U; i++) {
            x0 = x1; x1 = x2; x2 = x3; x3 = uv[i];
            float uc = fmaf(w0, x0, fmaf(w1, x1, fmaf(w2, x2, fmaf(w3, x3, bias))));
            float acc = Dp * uc;
            #pragma unroll
            for (int s = 0; s < DSTATE; s++) {
                st[s] = fmaf(st[s], Aval[s], uc);
                acc += st[s];
            }
            const float z = zv[i];
            const float sig = 1.0f / (1.0f + expf(-z));
            const float y = acc * (z * sig);
            const __nv_bfloat16 h = __float2bfloat16(y);
            const __nv_bfloat16 l = __float2bfloat16(y - __bfloat162float(h));
            const size_t o = (size_t)(t0 + i) * DINNER + d;
            yh[o] = h;
            yl[o] = l;
        }
    }
}

// ---------------------------------------------------------------------------
extern "C" void kernel_launch(void* const* d_in, const int* in_sizes, int n_in,
                              void* d_out, int out_size)
{
    const float* x       = (const float*)d_in[0];  // (B, L, DMODEL)
    const float* W_in    = (const float*)d_in[1];  // (DMODEL, 2*DINNER)
    const float* conv_w  = (const float*)d_in[2];
    const float* conv_b  = (const float*)d_in[3];
    const float* A_log   = (const float*)d_in[4];
    const float* D_param = (const float*)d_in[5];
    const float* W_out   = (const float*)d_in[6];  // (DINNER, DMODEL)
    float* out = (float*)d_out;                    // (B, L, DMODEL)

    float *xz_p;
    __nv_bfloat16 *xhi_p, *xlo_p, *winh_p, *winl_p, *wouth_p, *woutl_p, *yhi_p, *ylo_p;
    cudaGetSymbolAddress((void**)&xz_p,    g_xz);
    cudaGetSymbolAddress((void**)&xhi_p,   g_xhi);
    cudaGetSymbolAddress((void**)&xlo_p,   g_xlo);
    cudaGetSymbolAddress((void**)&winh_p,  g_WinT_hi);
    cudaGetSymbolAddress((void**)&winl_p,  g_WinT_lo);
    cudaGetSymbolAddress((void**)&wouth_p, g_WoutT_hi);
    cudaGetSymbolAddress((void**)&woutl_p, g_WoutT_lo);
    cudaGetSymbolAddress((void**)&yhi_p,   g_yhi);
    cudaGetSymbolAddress((void**)&ylo_p,   g_ylo);

    // 2 stages x 64KB + alignment pad  (opt-in above 48KB)
    const int GEMM_SMEM = 2 * 4 * 128 * 128 + 1024;
    cudaFuncSetAttribute(gemm_bf16x3,
                         cudaFuncAttributeMaxDynamicSharedMemorySize, GEMM_SMEM);

    // 1) Split x into bf16 hi/lo            (8192 x 1024)
    {
        const int n4 = MTOK * DMODEL / 4;
        split_f32<<<(n4 + 255) / 256, 256>>>(x, xhi_p, xlo_p, n4);
    }
    // 2) Transpose+split weights
    {
        dim3 blk(32, 8);
        dim3 g1(2 * DINNER / 32, DMODEL / 32);         // W_in: K=1024, N=4096
        transpose_split<<<g1, blk>>>(W_in, winh_p, winl_p, DMODEL, 2 * DINNER);
        dim3 g2(DMODEL / 32, DINNER / 32);             // W_out: K=2048, N=1024
        transpose_split<<<g2, blk>>>(W_out, wouth_p, woutl_p, DINNER, DMODEL);
    }
    // 3) GEMM1: xz = x @ W_in   -> fp32 (8192, 4096)
    {
        dim3 grid(2 * DINNER / 128, MTOK / 128);       // (32, 64)
        gemm_bf16x3<<<grid, 256, GEMM_SMEM>>>(MTOK, 2 * DINNER, DMODEL,
                                              xhi_p, xlo_p, winh_p, winl_p, xz_p);
    }
    // 4) Fused conv + scan + gate -> y hi/lo bf16
    conv_scan_gate<<<(BSZ * DINNER) / 64, 64>>>(conv_w, conv_b, A_log, D_param);
    // 5) GEMM2: out = y @ W_out -> fp32 (8192, 1024)
    {
        dim3 grid(DMODEL / 128, MTOK / 128);           // (8, 64)
        gemm_bf16x3<<<grid, 256, GEMM_SMEM>>>(MTOK, DMODEL, DINNER,
                                              yhi_p, ylo_p, wouth_p, woutl_p, out);
    }
}